// round 10
// baseline (speedup 1.0000x reference)
#include <cuda_runtime.h>
#include <cuda_fp16.h>
#include <cstdint>

#define NB 1024
#define NT 256
#define NC 512
#define NH 64

// ---------------- scratch (static device globals; no allocation) ----------------
__device__ __half g_q[NB*NT*NH];
__device__ __half g_k[NB*NT*NH];
__device__ __half g_v[NB*NT*NH];
__device__ __half g_wt[192*512];           // [n192][k] transposed fp16

// ---------------- helpers ----------------
__device__ __forceinline__ uint32_t smem_u32(const void* p){
  uint32_t a;
  asm("{ .reg .u64 t; cvta.to.shared.u64 t, %1; cvt.u32.u64 %0, t; }" : "=r"(a) : "l"(p));
  return a;
}
// fp16 MMA, fp32 accumulate
__device__ __forceinline__ void mma16816f(float* d, const uint32_t* a, const uint32_t* b){
  asm volatile(
    "mma.sync.aligned.m16n8k16.row.col.f32.f16.f16.f32 "
    "{%0,%1,%2,%3},{%4,%5,%6,%7},{%8,%9},{%0,%1,%2,%3};\n"
    : "+f"(d[0]), "+f"(d[1]), "+f"(d[2]), "+f"(d[3])
    : "r"(a[0]), "r"(a[1]), "r"(a[2]), "r"(a[3]), "r"(b[0]), "r"(b[1]));
}
__device__ __forceinline__ void cp_async16(uint32_t saddr, const void* g){
  asm volatile("cp.async.cg.shared.global [%0], [%1], 16;" :: "r"(saddr), "l"(g));
}
#define CP_COMMIT() asm volatile("cp.async.commit_group;" ::: "memory")
#define CP_WAIT0()  asm volatile("cp.async.wait_group 0;" ::: "memory")

// pack two fp32 base-2 exponents to half2 and take 2^x elementwise (one MUFU op)
__device__ __forceinline__ uint32_t ex2h2(float a, float b){
  __half2 t = __floats2half2_rn(a, b);
  uint32_t u = *reinterpret_cast<uint32_t*>(&t);
  uint32_t r;
  asm("ex2.approx.f16x2 %0, %1;" : "=r"(r) : "r"(u));
  return r;
}

// ---------------- kernel 0: transpose weights to fp16 ----------------
__global__ void prep_w_kernel(const float* __restrict__ Wq,
                              const float* __restrict__ Wk,
                              const float* __restrict__ Wv){
  int idx = blockIdx.x*blockDim.x + threadIdx.x;
  if (idx >= 192*512) return;
  int n192 = idx >> 9, k = idx & 511;
  int mat = n192 >> 6, n = n192 & 63;
  const float* W = (mat == 0) ? Wq : (mat == 1 ? Wk : Wv);
  g_wt[idx] = __float2half_rn(W[k*NH + n]);
}

// ---------------- kernel 1: fused QKV projection (fp16 single-pass MMA) ----------------
// unchanged from the 286.5us passing kernel
#define K1_WOFF  9216
#define K1_WBUF  13824
#define K1_SMEM  ((9216 + 2*13824)*2)

__global__ __launch_bounds__(256, 1) void qkv_kernel(const float* __restrict__ x){
  extern __shared__ __half sm1[];
  __half* xs = sm1;
  const uint32_t sb = smem_u32(sm1);

  const int t = threadIdx.x;
  const int w = t >> 5, lane = t & 31, g = lane >> 2, t4 = lane & 3;
  const int mw = w >> 2, nw = w & 3;          // 2(m) x 4(n)
  const int row0 = blockIdx.x * 128;

  float acc[4][6][4];
  #pragma unroll
  for (int mt = 0; mt < 4; mt++)
    #pragma unroll
    for (int nt = 0; nt < 6; nt++)
      #pragma unroll
      for (int e = 0; e < 4; e++) acc[mt][nt][e] = 0.f;

  float4 xr[8];

  #define LDG_X(kc) { \
    _Pragma("unroll") \
    for (int i = 0; i < 8; i++){ \
      int idx4 = i*256 + t; \
      int r = idx4 >> 4, c4 = (idx4 & 15) << 2; \
      xr[i] = *reinterpret_cast<const float4*>(x + (size_t)(row0 + r)*NC + (kc)*64 + c4); \
    } }

  #define STS_X() { \
    _Pragma("unroll") \
    for (int i = 0; i < 8; i++){ \
      int idx4 = i*256 + t; \
      int r = idx4 >> 4, c4 = (idx4 & 15) << 2; \
      float4 v = xr[i]; \
      __half2 h01 = __floats2half2_rn(v.x, v.y); \
      __half2 h23 = __floats2half2_rn(v.z, v.w); \
      *reinterpret_cast<__half2*>(&xs[r*72 + c4    ]) = h01; \
      *reinterpret_cast<__half2*>(&xs[r*72 + c4 + 2]) = h23; \
    } }

  #define CPA_W(kc, b) { \
    _Pragma("unroll") \
    for (int i = 0; i < 6; i++){ \
      int idx = i*256 + t; \
      int n = idx >> 3, c8 = idx & 7; \
      const __half* src = g_wt + n*512 + (kc)*64 + c8*8; \
      uint32_t dst = sb + (uint32_t)(K1_WOFF + (b)*K1_WBUF + n*72 + c8*8) * 2u; \
      cp_async16(dst, src); \
    } \
    CP_COMMIT(); }

  LDG_X(0); STS_X(); CPA_W(0, 0);

  for (int kc = 0; kc < 8; kc++){
    const int buf = kc & 1;
    CP_WAIT0();
    __syncthreads();

    if (kc < 7){
      CPA_W(kc+1, buf^1);
      LDG_X(kc+1);
    }

    const __half* wb = sm1 + K1_WOFF + buf*K1_WBUF;

    #pragma unroll
    for (int ks = 0; ks < 4; ks++){
      const int ko = ks*16;
      uint32_t ah[4][4];
      #pragma unroll
      for (int mt = 0; mt < 4; mt++){
        int rb = mw*64 + mt*16;
        ah[mt][0] = *reinterpret_cast<const uint32_t*>(&xs[(rb+g  )*72 + ko + 2*t4    ]);
        ah[mt][1] = *reinterpret_cast<const uint32_t*>(&xs[(rb+g+8)*72 + ko + 2*t4    ]);
        ah[mt][2] = *reinterpret_cast<const uint32_t*>(&xs[(rb+g  )*72 + ko + 2*t4 + 8]);
        ah[mt][3] = *reinterpret_cast<const uint32_t*>(&xs[(rb+g+8)*72 + ko + 2*t4 + 8]);
      }
      uint32_t bb[6][2];
      #pragma unroll
      for (int nt = 0; nt < 6; nt++){
        int nb = nw*48 + nt*8;
        bb[nt][0] = *reinterpret_cast<const uint32_t*>(&wb[(nb+g)*72 + ko + 2*t4    ]);
        bb[nt][1] = *reinterpret_cast<const uint32_t*>(&wb[(nb+g)*72 + ko + 2*t4 + 8]);
      }
      #pragma unroll
      for (int nt = 0; nt < 6; nt++)
        #pragma unroll
        for (int mt = 0; mt < 4; mt++) mma16816f(acc[mt][nt], ah[mt], bb[nt]);
    }

    __syncthreads();
    if (kc < 7){ STS_X(); }
  }

  // epilogue: fp32 accum -> fp16 scratch
  #pragma unroll
  for (int mt = 0; mt < 4; mt++){
    #pragma unroll
    for (int nt = 0; nt < 6; nt++){
      int col = nw*48 + nt*8 + 2*t4;
      int mat = col >> 6, h = col & 63;
      __half* dst = (mat == 0) ? g_q : (mat == 1 ? g_k : g_v);
      int r0g = row0 + mw*64 + mt*16 + g;
      *reinterpret_cast<__half2*>(&dst[(size_t)r0g*NH + h]) =
          __floats2half2_rn(acc[mt][nt][0], acc[mt][nt][1]);
      *reinterpret_cast<__half2*>(&dst[(size_t)(r0g+8)*NH + h]) =
          __floats2half2_rn(acc[mt][nt][2], acc[mt][nt][3]);
    }
  }
  #undef LDG_X
  #undef STS_X
  #undef CPA_W
}

// ---------------- kernel 2: causal attention (no online max, f16x2 ex2, MMA row-sums) ----------------
// smem (halves): q[9216] | k[18432] | vt[72*266] (rows 64-71: ones/zeros block for row sums)
#define A_Q  0
#define A_K  9216
#define A_V  27648
#define VSTR 266
#define A_TOT (A_V + 72*VSTR)
#define K2_SMEM (A_TOT*2)

// e = S_raw * 0.125 * log2(e) - 4   (fixed centering; cancels in P/sum(P))
#define ESCL 0.18033688f
#define EOFF (-4.0f)

__global__ __launch_bounds__(256, 2) void attn_kernel(float* __restrict__ out){
  extern __shared__ __half sm2[];
  __half* qs = sm2 + A_Q;
  __half* ks = sm2 + A_K;
  __half* vt = sm2 + A_V;

  const int b   = blockIdx.x >> 1;
  const int blk = blockIdx.x & 1;
  const int t = threadIdx.x, w = t >> 5, lane = t & 31, g = lane >> 2, t4 = lane & 3;
  const int nk = (blk + 1) * 128;
  const size_t base = (size_t)b * (NT*NH);

  // stage Q (128 rows)
  #pragma unroll
  for (int i = 0; i < 8; i++){
    int idx4 = i*256 + t;
    int r = idx4 >> 4, c4 = (idx4 & 15) << 2;
    *reinterpret_cast<uint2*>(&qs[r*72 + c4]) =
        *reinterpret_cast<const uint2*>(&g_q[base + (size_t)(blk*128 + r)*NH + c4]);
  }
  // stage K (rows 0..nk)
  for (int idx4 = t; idx4 < nk*16; idx4 += 256){
    int r = idx4 >> 4, c4 = (idx4 & 15) << 2;
    *reinterpret_cast<uint2*>(&ks[r*72 + c4]) =
        *reinterpret_cast<const uint2*>(&g_k[base + (size_t)r*NH + c4]);
  }
  // stage V transposed: vt[h][s]
  for (int idx4 = t; idx4 < nk*16; idx4 += 256){
    int s = idx4 >> 4, h4 = (idx4 & 15) << 2;
    uint2 v2 = *reinterpret_cast<const uint2*>(&g_v[base + (size_t)s*NH + h4]);
    const __half2* pv = reinterpret_cast<const __half2*>(&v2);
    vt[(h4+0)*VSTR + s] = __low2half(pv[0]);  vt[(h4+1)*VSTR + s] = __high2half(pv[0]);
    vt[(h4+2)*VSTR + s] = __low2half(pv[1]);  vt[(h4+3)*VSTR + s] = __high2half(pv[1]);
  }
  // ones/zeros block rows 64..71 (row 64 = ones -> row sums via MMA)
  {
    const __half one  = __float2half(1.0f);
    const __half zero = __float2half(0.0f);
    for (int idx = t; idx < 8*NT; idx += 256){
      int hr = idx >> 8, s = idx & 255;
      vt[(64+hr)*VSTR + s] = (hr == 0) ? one : zero;
    }
  }
  __syncthreads();

  const int rb  = blk*128 + w*16;
  const int lrb = w*16;

  // hoist Q fragments (loop-invariant over j)
  uint32_t qa[4][4];
  #pragma unroll
  for (int ks_ = 0; ks_ < 4; ks_++){
    int ko = ks_*16;
    qa[ks_][0] = *reinterpret_cast<const uint32_t*>(&qs[(lrb+g  )*72 + ko + 2*t4    ]);
    qa[ks_][1] = *reinterpret_cast<const uint32_t*>(&qs[(lrb+g+8)*72 + ko + 2*t4    ]);
    qa[ks_][2] = *reinterpret_cast<const uint32_t*>(&qs[(lrb+g  )*72 + ko + 2*t4 + 8]);
    qa[ks_][3] = *reinterpret_cast<const uint32_t*>(&qs[(lrb+g+8)*72 + ko + 2*t4 + 8]);
  }

  float o[8][4];
  float ol[4];
  #pragma unroll
  for (int nt = 0; nt < 8; nt++)
    #pragma unroll
    for (int e = 0; e < 4; e++) o[nt][e] = 0.f;
  #pragma unroll
  for (int e = 0; e < 4; e++) ol[e] = 0.f;

  const int jmax = (rb + 15) >> 6;
  for (int j = 0; j <= jmax; j++){
    float s[8][4];
    #pragma unroll
    for (int nt = 0; nt < 8; nt++)
      #pragma unroll
      for (int e = 0; e < 4; e++) s[nt][e] = 0.f;

    // ---- S = Q K^T ----
    #pragma unroll
    for (int ks_ = 0; ks_ < 4; ks_++){
      int ko = ks_*16;
      #pragma unroll
      for (int nt = 0; nt < 8; nt++){
        int kr = j*64 + nt*8 + g;
        uint32_t kb[2];
        kb[0] = *reinterpret_cast<const uint32_t*>(&ks[kr*72 + ko + 2*t4    ]);
        kb[1] = *reinterpret_cast<const uint32_t*>(&ks[kr*72 + ko + 2*t4 + 8]);
        mma16816f(s[nt], qa[ks_], kb);
      }
    }

    // ---- P = 2^(S*scale - 4) with causal mask, then O += P V (incl. ones col = row sums) ----
    const bool needm = (j*64 + 63 > rb);
    #pragma unroll
    for (int ks2 = 0; ks2 < 4; ks2++){
      uint32_t ph[4];
      #pragma unroll
      for (int h = 0; h < 2; h++){
        const int nt = 2*ks2 + h;
        float e0 = fmaf(s[nt][0], ESCL, EOFF);
        float e1 = fmaf(s[nt][1], ESCL, EOFF);
        float e2 = fmaf(s[nt][2], ESCL, EOFF);
        float e3 = fmaf(s[nt][3], ESCL, EOFF);
        if (needm){
          int c0 = j*64 + nt*8 + 2*t4;
          int r0 = rb + g, r1 = rb + g + 8;
          if (c0     > r0) e0 = -1e30f;
          if (c0 + 1 > r0) e1 = -1e30f;
          if (c0     > r1) e2 = -1e30f;
          if (c0 + 1 > r1) e3 = -1e30f;
        }
        ph[2*h    ] = ex2h2(e0, e1);
        ph[2*h + 1] = ex2h2(e2, e3);
      }
      const int sb2 = j*64 + ks2*16;
      #pragma unroll
      for (int nt2 = 0; nt2 < 8; nt2++){
        uint32_t vb[2];
        vb[0] = *reinterpret_cast<const uint32_t*>(&vt[(nt2*8+g)*VSTR + sb2 + 2*t4    ]);
        vb[1] = *reinterpret_cast<const uint32_t*>(&vt[(nt2*8+g)*VSTR + sb2 + 2*t4 + 8]);
        mma16816f(o[nt2], ph, vb);
      }
      { // ones-column block (rows 64-71 of vt): accumulates row sums l into ol
        uint32_t vb[2];
        vb[0] = *reinterpret_cast<const uint32_t*>(&vt[(64+g)*VSTR + sb2 + 2*t4    ]);
        vb[1] = *reinterpret_cast<const uint32_t*>(&vt[(64+g)*VSTR + sb2 + 2*t4 + 8]);
        mma16816f(ol, ph, vb);
      }
    }
  }

  // ---- extract row sums (col 64 lives in lanes with t4==0) and normalize ----
  const int qb = (lane >> 2) << 2;
  float l0 = __shfl_sync(0xffffffffu, ol[0], qb);
  float l1 = __shfl_sync(0xffffffffu, ol[2], qb);
  float inv0 = 1.f / l0, inv1 = 1.f / l1;

  #pragma unroll
  for (int nt2 = 0; nt2 < 8; nt2++){
    int col = nt2*8 + 2*t4;
    size_t o0 = base + (size_t)(rb + g)*NH + col;
    float2 v01 = make_float2(o[nt2][0]*inv0, o[nt2][1]*inv0);
    float2 v23 = make_float2(o[nt2][2]*inv1, o[nt2][3]*inv1);
    *reinterpret_cast<float2*>(&out[o0])        = v01;
    *reinterpret_cast<float2*>(&out[o0 + 8*NH]) = v23;
  }
}

// ---------------- launch ----------------
extern "C" void kernel_launch(void* const* d_in, const int* in_sizes, int n_in,
                              void* d_out, int out_size){
  const float* x  = (const float*)d_in[0];
  const float* Wq = (const float*)d_in[1];
  const float* Wk = (const float*)d_in[2];
  const float* Wv = (const float*)d_in[3];
  float* out = (float*)d_out;

  cudaFuncSetAttribute(qkv_kernel,  cudaFuncAttributeMaxDynamicSharedMemorySize, K1_SMEM);
  cudaFuncSetAttribute(attn_kernel, cudaFuncAttributeMaxDynamicSharedMemorySize, K2_SMEM);

  prep_w_kernel<<<384, 256>>>(Wq, Wk, Wv);
  qkv_kernel<<<2048, 256, K1_SMEM>>>(x);
  attn_kernel<<<2048, 256, K2_SMEM>>>(out);
}

// round 11
// speedup vs baseline: 1.5103x; 1.5103x over previous
#include <cuda_runtime.h>
#include <cuda_fp16.h>
#include <cstdint>

#define NB 1024
#define NT 256
#define NC 512
#define NH 64

// ---------------- scratch (static device globals; no allocation) ----------------
__device__ __half g_q[NB*NT*NH];
__device__ __half g_k[NB*NT*NH];
__device__ __half g_v[NB*NT*NH];
__device__ __half g_wt[192*512];           // [n192][k] transposed fp16

// ---------------- helpers ----------------
__device__ __forceinline__ uint32_t smem_u32(const void* p){
  uint32_t a;
  asm("{ .reg .u64 t; cvta.to.shared.u64 t, %1; cvt.u32.u64 %0, t; }" : "=r"(a) : "l"(p));
  return a;
}
// fp16 MMA, fp32 accumulate
__device__ __forceinline__ void mma16816f(float* d, const uint32_t* a, const uint32_t* b){
  asm volatile(
    "mma.sync.aligned.m16n8k16.row.col.f32.f16.f16.f32 "
    "{%0,%1,%2,%3},{%4,%5,%6,%7},{%8,%9},{%0,%1,%2,%3};\n"
    : "+f"(d[0]), "+f"(d[1]), "+f"(d[2]), "+f"(d[3])
    : "r"(a[0]), "r"(a[1]), "r"(a[2]), "r"(a[3]), "r"(b[0]), "r"(b[1]));
}
__device__ __forceinline__ void cp_async16(uint32_t saddr, const void* g){
  asm volatile("cp.async.cg.shared.global [%0], [%1], 16;" :: "r"(saddr), "l"(g));
}
#define CP_COMMIT() asm volatile("cp.async.commit_group;" ::: "memory")
#define CP_WAIT0()  asm volatile("cp.async.wait_group 0;" ::: "memory")

__device__ __forceinline__ uint32_t packh2(float a, float b){
  __half2 t = __floats2half2_rn(a, b);
  return *reinterpret_cast<uint32_t*>(&t);
}
// single-MUFU 2^x (fp32)
__device__ __forceinline__ float ex2f(float x){
  float r; asm("ex2.approx.f32 %0, %1;" : "=f"(r) : "f"(x)); return r;
}

// ---------------- kernel 0: transpose weights to fp16 ----------------
__global__ void prep_w_kernel(const float* __restrict__ Wq,
                              const float* __restrict__ Wk,
                              const float* __restrict__ Wv){
  int idx = blockIdx.x*blockDim.x + threadIdx.x;
  if (idx >= 192*512) return;
  int n192 = idx >> 9, k = idx & 511;
  int mat = n192 >> 6, n = n192 & 63;
  const float* W = (mat == 0) ? Wq : (mat == 1 ? Wk : Wv);
  g_wt[idx] = __float2half_rn(W[k*NH + n]);
}

// ---------------- kernel 1: fused QKV projection (fp16 single-pass MMA) ----------------
// byte-identical to the 286.5us passing kernel
#define K1_WOFF  9216
#define K1_WBUF  13824
#define K1_SMEM  ((9216 + 2*13824)*2)

__global__ __launch_bounds__(256, 1) void qkv_kernel(const float* __restrict__ x){
  extern __shared__ __half sm1[];
  __half* xs = sm1;
  const uint32_t sb = smem_u32(sm1);

  const int t = threadIdx.x;
  const int w = t >> 5, lane = t & 31, g = lane >> 2, t4 = lane & 3;
  const int mw = w >> 2, nw = w & 3;          // 2(m) x 4(n)
  const int row0 = blockIdx.x * 128;

  float acc[4][6][4];
  #pragma unroll
  for (int mt = 0; mt < 4; mt++)
    #pragma unroll
    for (int nt = 0; nt < 6; nt++)
      #pragma unroll
      for (int e = 0; e < 4; e++) acc[mt][nt][e] = 0.f;

  float4 xr[8];

  #define LDG_X(kc) { \
    _Pragma("unroll") \
    for (int i = 0; i < 8; i++){ \
      int idx4 = i*256 + t; \
      int r = idx4 >> 4, c4 = (idx4 & 15) << 2; \
      xr[i] = *reinterpret_cast<const float4*>(x + (size_t)(row0 + r)*NC + (kc)*64 + c4); \
    } }

  #define STS_X() { \
    _Pragma("unroll") \
    for (int i = 0; i < 8; i++){ \
      int idx4 = i*256 + t; \
      int r = idx4 >> 4, c4 = (idx4 & 15) << 2; \
      float4 v = xr[i]; \
      __half2 h01 = __floats2half2_rn(v.x, v.y); \
      __half2 h23 = __floats2half2_rn(v.z, v.w); \
      *reinterpret_cast<__half2*>(&xs[r*72 + c4    ]) = h01; \
      *reinterpret_cast<__half2*>(&xs[r*72 + c4 + 2]) = h23; \
    } }

  #define CPA_W(kc, b) { \
    _Pragma("unroll") \
    for (int i = 0; i < 6; i++){ \
      int idx = i*256 + t; \
      int n = idx >> 3, c8 = idx & 7; \
      const __half* src = g_wt + n*512 + (kc)*64 + c8*8; \
      uint32_t dst = sb + (uint32_t)(K1_WOFF + (b)*K1_WBUF + n*72 + c8*8) * 2u; \
      cp_async16(dst, src); \
    } \
    CP_COMMIT(); }

  LDG_X(0); STS_X(); CPA_W(0, 0);

  for (int kc = 0; kc < 8; kc++){
    const int buf = kc & 1;
    CP_WAIT0();
    __syncthreads();

    if (kc < 7){
      CPA_W(kc+1, buf^1);
      LDG_X(kc+1);
    }

    const __half* wb = sm1 + K1_WOFF + buf*K1_WBUF;

    #pragma unroll
    for (int ks = 0; ks < 4; ks++){
      const int ko = ks*16;
      uint32_t ah[4][4];
      #pragma unroll
      for (int mt = 0; mt < 4; mt++){
        int rb = mw*64 + mt*16;
        ah[mt][0] = *reinterpret_cast<const uint32_t*>(&xs[(rb+g  )*72 + ko + 2*t4    ]);
        ah[mt][1] = *reinterpret_cast<const uint32_t*>(&xs[(rb+g+8)*72 + ko + 2*t4    ]);
        ah[mt][2] = *reinterpret_cast<const uint32_t*>(&xs[(rb+g  )*72 + ko + 2*t4 + 8]);
        ah[mt][3] = *reinterpret_cast<const uint32_t*>(&xs[(rb+g+8)*72 + ko + 2*t4 + 8]);
      }
      uint32_t bb[6][2];
      #pragma unroll
      for (int nt = 0; nt < 6; nt++){
        int nb = nw*48 + nt*8;
        bb[nt][0] = *reinterpret_cast<const uint32_t*>(&wb[(nb+g)*72 + ko + 2*t4    ]);
        bb[nt][1] = *reinterpret_cast<const uint32_t*>(&wb[(nb+g)*72 + ko + 2*t4 + 8]);
      }
      #pragma unroll
      for (int nt = 0; nt < 6; nt++)
        #pragma unroll
        for (int mt = 0; mt < 4; mt++) mma16816f(acc[mt][nt], ah[mt], bb[nt]);
    }

    __syncthreads();
    if (kc < 7){ STS_X(); }
  }

  // epilogue: fp32 accum -> fp16 scratch
  #pragma unroll
  for (int mt = 0; mt < 4; mt++){
    #pragma unroll
    for (int nt = 0; nt < 6; nt++){
      int col = nw*48 + nt*8 + 2*t4;
      int mat = col >> 6, h = col & 63;
      __half* dst = (mat == 0) ? g_q : (mat == 1 ? g_k : g_v);
      int r0g = row0 + mw*64 + mt*16 + g;
      *reinterpret_cast<__half2*>(&dst[(size_t)r0g*NH + h]) =
          __floats2half2_rn(acc[mt][nt][0], acc[mt][nt][1]);
      *reinterpret_cast<__half2*>(&dst[(size_t)(r0g+8)*NH + h]) =
          __floats2half2_rn(acc[mt][nt][2], acc[mt][nt][3]);
    }
  }
  #undef LDG_X
  #undef STS_X
  #undef CPA_W
}

// ---------------- kernel 2: causal attention (fixed-center softmax, fp32 ex2, per-thread sums) ----------------
// smem (halves): q[9216] | k[18432] | vt[64*266]   (same as the 286.5us kernel)
#define A_Q  0
#define A_K  9216
#define A_V  27648
#define VSTR 266
#define A_TOT (A_V + 64*VSTR)
#define K2_SMEM (A_TOT*2)

// e = S_raw * 0.125 * log2(e) - 4  (fixed centering; cancels in P/sum(P))
#define ESCL 0.18033688f
#define EOFF (-4.0f)

__global__ __launch_bounds__(256, 2) void attn_kernel(float* __restrict__ out){
  extern __shared__ __half sm2[];
  __half* qs = sm2 + A_Q;
  __half* ks = sm2 + A_K;
  __half* vt = sm2 + A_V;

  const int b   = blockIdx.x >> 1;
  const int blk = blockIdx.x & 1;
  const int t = threadIdx.x, w = t >> 5, lane = t & 31, g = lane >> 2, t4 = lane & 3;
  const int nk = (blk + 1) * 128;
  const size_t base = (size_t)b * (NT*NH);

  // stage Q (128 rows)
  #pragma unroll
  for (int i = 0; i < 8; i++){
    int idx4 = i*256 + t;
    int r = idx4 >> 4, c4 = (idx4 & 15) << 2;
    *reinterpret_cast<uint2*>(&qs[r*72 + c4]) =
        *reinterpret_cast<const uint2*>(&g_q[base + (size_t)(blk*128 + r)*NH + c4]);
  }
  // stage K (rows 0..nk)
  for (int idx4 = t; idx4 < nk*16; idx4 += 256){
    int r = idx4 >> 4, c4 = (idx4 & 15) << 2;
    *reinterpret_cast<uint2*>(&ks[r*72 + c4]) =
        *reinterpret_cast<const uint2*>(&g_k[base + (size_t)r*NH + c4]);
  }
  // stage V transposed: vt[h][s]
  for (int idx4 = t; idx4 < nk*16; idx4 += 256){
    int s = idx4 >> 4, h4 = (idx4 & 15) << 2;
    uint2 v2 = *reinterpret_cast<const uint2*>(&g_v[base + (size_t)s*NH + h4]);
    const __half2* pv = reinterpret_cast<const __half2*>(&v2);
    vt[(h4+0)*VSTR + s] = __low2half(pv[0]);  vt[(h4+1)*VSTR + s] = __high2half(pv[0]);
    vt[(h4+2)*VSTR + s] = __low2half(pv[1]);  vt[(h4+3)*VSTR + s] = __high2half(pv[1]);
  }
  __syncthreads();

  const int rb  = blk*128 + w*16;
  const int lrb = w*16;

  // hoist Q fragments (loop-invariant over j)
  uint32_t qa[4][4];
  #pragma unroll
  for (int ks_ = 0; ks_ < 4; ks_++){
    int ko = ks_*16;
    qa[ks_][0] = *reinterpret_cast<const uint32_t*>(&qs[(lrb+g  )*72 + ko + 2*t4    ]);
    qa[ks_][1] = *reinterpret_cast<const uint32_t*>(&qs[(lrb+g+8)*72 + ko + 2*t4    ]);
    qa[ks_][2] = *reinterpret_cast<const uint32_t*>(&qs[(lrb+g  )*72 + ko + 2*t4 + 8]);
    qa[ks_][3] = *reinterpret_cast<const uint32_t*>(&qs[(lrb+g+8)*72 + ko + 2*t4 + 8]);
  }

  float o[8][4];
  #pragma unroll
  for (int nt = 0; nt < 8; nt++)
    #pragma unroll
    for (int e = 0; e < 4; e++) o[nt][e] = 0.f;
  float rs0 = 0.f, rs1 = 0.f;          // per-thread partial row sums (rows rb+g, rb+g+8)

  const int jmax = (rb + 15) >> 6;
  for (int j = 0; j <= jmax; j++){
    float s[8][4];
    #pragma unroll
    for (int nt = 0; nt < 8; nt++)
      #pragma unroll
      for (int e = 0; e < 4; e++) s[nt][e] = 0.f;

    // ---- S = Q K^T ----
    #pragma unroll
    for (int ks_ = 0; ks_ < 4; ks_++){
      int ko = ks_*16;
      #pragma unroll
      for (int nt = 0; nt < 8; nt++){
        int kr = j*64 + nt*8 + g;
        uint32_t kb[2];
        kb[0] = *reinterpret_cast<const uint32_t*>(&ks[kr*72 + ko + 2*t4    ]);
        kb[1] = *reinterpret_cast<const uint32_t*>(&ks[kr*72 + ko + 2*t4 + 8]);
        mma16816f(s[nt], qa[ks_], kb);
      }
    }

    // ---- P = 2^(S*scale - 4) with causal mask; accumulate per-thread row sums ----
    const bool needm = (j*64 + 63 > rb);
    #pragma unroll
    for (int nt = 0; nt < 8; nt++){
      float e0 = fmaf(s[nt][0], ESCL, EOFF);
      float e1 = fmaf(s[nt][1], ESCL, EOFF);
      float e2 = fmaf(s[nt][2], ESCL, EOFF);
      float e3 = fmaf(s[nt][3], ESCL, EOFF);
      if (needm){
        int c0 = j*64 + nt*8 + 2*t4;
        int r0 = rb + g, r1 = rb + g + 8;
        if (c0     > r0) e0 = -1e30f;
        if (c0 + 1 > r0) e1 = -1e30f;
        if (c0     > r1) e2 = -1e30f;
        if (c0 + 1 > r1) e3 = -1e30f;
      }
      s[nt][0] = ex2f(e0); rs0 += s[nt][0];
      s[nt][1] = ex2f(e1); rs0 += s[nt][1];
      s[nt][2] = ex2f(e2); rs1 += s[nt][2];
      s[nt][3] = ex2f(e3); rs1 += s[nt][3];
    }

    // ---- O += P V ----
    #pragma unroll
    for (int ks2 = 0; ks2 < 4; ks2++){
      uint32_t ph[4];
      ph[0] = packh2(s[2*ks2  ][0], s[2*ks2  ][1]);
      ph[1] = packh2(s[2*ks2  ][2], s[2*ks2  ][3]);
      ph[2] = packh2(s[2*ks2+1][0], s[2*ks2+1][1]);
      ph[3] = packh2(s[2*ks2+1][2], s[2*ks2+1][3]);
      int sb2 = j*64 + ks2*16;
      #pragma unroll
      for (int nt2 = 0; nt2 < 8; nt2++){
        uint32_t vb[2];
        vb[0] = *reinterpret_cast<const uint32_t*>(&vt[(nt2*8+g)*VSTR + sb2 + 2*t4    ]);
        vb[1] = *reinterpret_cast<const uint32_t*>(&vt[(nt2*8+g)*VSTR + sb2 + 2*t4 + 8]);
        mma16816f(o[nt2], ph, vb);
      }
    }
  }

  // ---- single end-of-kernel row-sum reduce across the t4 quad ----
  rs0 += __shfl_xor_sync(0xffffffffu, rs0, 1);
  rs0 += __shfl_xor_sync(0xffffffffu, rs0, 2);
  rs1 += __shfl_xor_sync(0xffffffffu, rs1, 1);
  rs1 += __shfl_xor_sync(0xffffffffu, rs1, 2);
  float inv0 = 1.f / rs0, inv1 = 1.f / rs1;

  #pragma unroll
  for (int nt2 = 0; nt2 < 8; nt2++){
    int col = nt2*8 + 2*t4;
    size_t o0 = base + (size_t)(rb + g)*NH + col;
    float2 v01 = make_float2(o[nt2][0]*inv0, o[nt2][1]*inv0);
    float2 v23 = make_float2(o[nt2][2]*inv1, o[nt2][3]*inv1);
    *reinterpret_cast<float2*>(&out[o0])        = v01;
    *reinterpret_cast<float2*>(&out[o0 + 8*NH]) = v23;
  }
}

// ---------------- launch ----------------
extern "C" void kernel_launch(void* const* d_in, const int* in_sizes, int n_in,
                              void* d_out, int out_size){
  const float* x  = (const float*)d_in[0];
  const float* Wq = (const float*)d_in[1];
  const float* Wk = (const float*)d_in[2];
  const float* Wv = (const float*)d_in[3];
  float* out = (float*)d_out;

  cudaFuncSetAttribute(qkv_kernel,  cudaFuncAttributeMaxDynamicSharedMemorySize, K1_SMEM);
  cudaFuncSetAttribute(attn_kernel, cudaFuncAttributeMaxDynamicSharedMemorySize, K2_SMEM);

  prep_w_kernel<<<384, 256>>>(Wq, Wk, Wv);
  qkv_kernel<<<2048, 256, K1_SMEM>>>(x);
  attn_kernel<<<2048, 256, K2_SMEM>>>(out);
}